// round 13
// baseline (speedup 1.0000x reference)
#include <cuda_runtime.h>
#include <cuda_bf16.h>
#include <math.h>

typedef unsigned long long ull;

#define N_NODES 50000
#define E_EDGES 600000
#define B_GR    128
#define D       128
#define NHEAD   4
#define DH      32
#define NEG_SLOPE 0.2f
#define SCAN_NBLK ((N_NODES + 255) / 256)   // 196
#define EB ((E_EDGES + 255) / 256)          // 2344
#define WB ((N_NODES * 32 + 255) / 256)     // 6250

// ---------------- device scratch (zero-initialized at module load) ----------------
__device__ int   d_src[E_EDGES];
__device__ int   d_dst[E_EDGES];
__device__ int   d_gid[N_NODES];
__device__ int   d_count[N_NODES];          // self-cleaning: decode +1, fill -1
__device__ int   d_rowptr[N_NODES + 1];
__device__ int   d_col[E_EDGES];
__device__ float d_z[N_NODES * D];
__device__ float d_as[N_NODES * NHEAD];
__device__ float d_ad[N_NODES * NHEAD];
__device__ float d_hA[N_NODES * D];
__device__ float d_hB[N_NODES * D];
__device__ float d_z0[D];
__device__ float d_gsum[B_GR * D];
__device__ int   d_gcnt[B_GR];

// ---------------- helpers ----------------
__device__ __forceinline__ float lrelu(float x) { return x >= 0.f ? x : NEG_SLOPE * x; }
__device__ __forceinline__ float eluf(float x)  { return x > 0.f ? x : expm1f(x); }
__device__ __forceinline__ void ffma2(ull &d, ull a, ull b) {
    asm("fma.rn.f32x2 %0, %1, %2, %0;" : "+l"(d) : "l"(a), "l"(b));
}
__device__ __forceinline__ ull dup2(float v) {
    ull r;
    asm("mov.b64 %0, {%1, %1};" : "=l"(r) : "f"(v));
    return r;
}

// int64 LE with values < 2^31 -> every odd 32-bit word is 0. Checking 8 fixed
// words: for int32 data these are random node ids, P(all 8 == 0) ~ (2e-5)^8.
__device__ __forceinline__ int detect_is64(const int* __restrict__ edge32) {
    int is64 = 1;
#pragma unroll
    for (int q = 0; q < 8; q++) is64 &= (edge32[2 * q + 1] == 0);
    return is64;
}

// ---------------- decode edges+ptr + histogram + z0 + gsum zero (one kernel) ----------------
__global__ void decode_k(const void* __restrict__ edge, const void* __restrict__ ptr,
                         const float* __restrict__ emb, const float* __restrict__ W0) {
    int b = blockIdx.x;
    int t = threadIdx.x;
    __shared__ int s_is64;
    if (t == 0) s_is64 = detect_is64((const int*)edge);
    __syncthreads();
    int is64 = s_is64;

    if (b < EB) {
        int e = b * 256 + t;
        if (e >= E_EDGES) return;
        int s, d;
        if (is64) {
            const long long* p = (const long long*)edge;
            s = (int)p[e]; d = (int)p[E_EDGES + e];
        } else {
            const int* p = (const int*)edge;
            s = p[e]; d = p[E_EDGES + e];
        }
        d_src[e] = s; d_dst[e] = d;
        atomicAdd(&d_count[d], 1);
    } else if (b < EB + SCAN_NBLK) {
        int n = (b - EB) * 256 + t;
        if (n >= N_NODES) return;
        d_gid[n] = is64 ? (int)((const long long*)ptr)[n] : ((const int*)ptr)[n];
    } else if (b < EB + SCAN_NBLK + 64) {
        int i = (b - EB - SCAN_NBLK) * 256 + t;
        if (i < B_GR * D) d_gsum[i] = 0.f;
        if (i < B_GR)     d_gcnt[i] = 0;
    } else {
        if (t < D) {
            float acc = 0.f;
            for (int k = 0; k < D; k++) acc += emb[k] * W0[k * D + t];
            d_z0[t] = acc;
        }
    }
}

// ---------------- single-kernel exclusive scan (redundant block prefixes) ----------------
__global__ void scan_k() {
    __shared__ int red[256];
    __shared__ int sh[256];
    int b = blockIdx.x;
    int t = threadIdx.x;
    if (b == 0 && t == 0) d_rowptr[N_NODES] = E_EDGES;

    // prefix = sum of counts[0 .. b*256)
    int limit = b * 256;
    int psum = 0;
    for (int i = t; i < limit; i += 256) psum += d_count[i];
    red[t] = psum;
    __syncthreads();
    for (int off = 128; off > 0; off >>= 1) {
        if (t < off) red[t] += red[t + off];
        __syncthreads();
    }
    int pre = red[0];

    // local inclusive scan of this block's 256 counts
    int i = limit + t;
    int v = (i < N_NODES) ? d_count[i] : 0;
    sh[t] = v;
    __syncthreads();
    for (int off = 1; off < 256; off <<= 1) {
        int tv = (t >= off) ? sh[t - off] : 0;
        __syncthreads();
        sh[t] += tv;
        __syncthreads();
    }
    if (i < N_NODES) d_rowptr[i] = pre + sh[t] - v;  // exclusive
}

// ---------------- CSR fill (self-cleaning counters) + layer-1 shortcut ----------------
__global__ void fill_h1_k(const float* __restrict__ emb) {
    int b = blockIdx.x;
    if (b < EB) {
        int e = b * 256 + threadIdx.x;
        if (e >= E_EDGES) return;
        int d = d_dst[e];
        int old = atomicSub(&d_count[d], 1);     // counters return to 0 for next run
        d_col[d_rowptr[d] + old - 1] = d_src[e];
    } else {
        int i = (b - EB) * 256 + threadIdx.x;    // float4 index
        if (i >= N_NODES * 32) return;
        int n = i >> 5, q = i & 31;
        int deg = d_rowptr[n + 1] - d_rowptr[n]; // race-free (count is being decremented)
        float m = (float)(deg + 2);              // 1 + deg_total, deg_total = deg + 1
        float4 z = ((const float4*)d_z0)[q];
        float4 e4 = ((const float4*)emb)[q];
        float4 o;
        o.x = eluf(m * z.x) + e4.x;
        o.y = eluf(m * z.y) + e4.y;
        o.z = eluf(m * z.z) + e4.z;
        o.w = eluf(m * z.w) + e4.w;
        ((float4*)d_hA)[i] = o;
    }
}

// ---------------- GEMM: z = h @ W via packed fma.rn.f32x2 ----------------
// 128 rows x 128 cols per block, 512 threads. ty=tid/16 -> 4 rows (ty*4+i),
// tx=tid&15 -> 4 col-pairs: ull indices {2tx, 2tx+1, 2tx+32, 2tx+33}
// (columns 4tx..4tx+3 and 64+4tx..64+4tx+3). All inner-loop shared reads are
// LDS.128. Hs2 padded to 130 ull/row so LDS.128 addresses stay 16B-aligned.
__global__ __launch_bounds__(512, 2) void gemm_k(const float* __restrict__ W, int sel) {
    const float* __restrict__ hin = sel ? d_hB : d_hA;
    __shared__ __align__(16) ull Ws[32 * 64];     // 16 KB: kk-row of 128 floats
    __shared__ __align__(16) ull Hs2[32 * 130];   // 33.3 KB: {h,h} dup, k-major
    int tid = threadIdx.x;
    int tx = tid & 15, ty = tid >> 4;             // ty 0..31
    int row0 = blockIdx.x * 128;

    ull acc[4][4];
#pragma unroll
    for (int i = 0; i < 4; i++)
#pragma unroll
        for (int j = 0; j < 4; j++) acc[i][j] = 0ull;

    for (int k0 = 0; k0 < 128; k0 += 32) {
        if (k0) __syncthreads();
        // load W chunk: 32 k x 128 cols = 1024 float4, 2 per thread
#pragma unroll
        for (int i = 0; i < 2; i++) {
            int idx = tid + i * 512;
            int kk = idx >> 5, c4 = idx & 31;
            ((float4*)Ws)[kk * 32 + c4] = ((const float4*)W)[(k0 + kk) * 32 + c4];
        }
        // load H chunk duplicated: Hs2[k*130 + r] = {h,h}
#pragma unroll
        for (int i = 0; i < 2; i++) {
            int idx = tid + i * 512;
            int r = idx >> 3, k4 = idx & 7;
            int row = row0 + r;
            float4 v = make_float4(0.f, 0.f, 0.f, 0.f);
            if (row < N_NODES) v = ((const float4*)hin)[row * 32 + (k0 >> 2) + k4];
            Hs2[(k4 * 4 + 0) * 130 + r] = dup2(v.x);
            Hs2[(k4 * 4 + 1) * 130 + r] = dup2(v.y);
            Hs2[(k4 * 4 + 2) * 130 + r] = dup2(v.z);
            Hs2[(k4 * 4 + 3) * 130 + r] = dup2(v.w);
        }
        __syncthreads();
#pragma unroll 8
        for (int kk = 0; kk < 32; kk++) {
            const ull* wrow = Ws + kk * 64;
            ulonglong2 b01 = *((const ulonglong2*)wrow + tx);        // ull 2tx,2tx+1
            ulonglong2 b23 = *((const ulonglong2*)wrow + tx + 16);   // ull 2tx+32,2tx+33
            const ull* arow = Hs2 + kk * 130 + ty * 4;
            ulonglong2 a01 = *(const ulonglong2*)arow;
            ulonglong2 a23 = *(const ulonglong2*)(arow + 2);
            ull a[4] = {a01.x, a01.y, a23.x, a23.y};
            ull bb[4] = {b01.x, b01.y, b23.x, b23.y};
#pragma unroll
            for (int i = 0; i < 4; i++)
#pragma unroll
                for (int j = 0; j < 4; j++) ffma2(acc[i][j], a[i], bb[j]);
        }
    }
#pragma unroll
    for (int i = 0; i < 4; i++) {
        int row = row0 + ty * 4 + i;
        if (row < N_NODES) {
            ull* zrow = (ull*)(d_z + row * D);
            zrow[2 * tx]      = acc[i][0];
            zrow[2 * tx + 1]  = acc[i][1];
            zrow[2 * tx + 32] = acc[i][2];
            zrow[2 * tx + 33] = acc[i][3];
        }
    }
}

// ---------------- attention logits a_s, a_d ----------------
__global__ void att_k(const float* __restrict__ att_s, const float* __restrict__ att_d) {
    int warp = (blockIdx.x * blockDim.x + threadIdx.x) >> 5;
    if (warp >= N_NODES) return;
    int lane = threadIdx.x & 31;
    int head = lane >> 3;
    float4 z = ((const float4*)d_z)[warp * 32 + lane];
    float4 s = ((const float4*)att_s)[head * 8 + (lane & 7)];
    float4 t = ((const float4*)att_d)[head * 8 + (lane & 7)];
    float ps = z.x * s.x + z.y * s.y + z.z * s.z + z.w * s.w;
    float pd = z.x * t.x + z.y * t.y + z.z * t.z + z.w * t.w;
#pragma unroll
    for (int o = 4; o >= 1; o >>= 1) {
        ps += __shfl_xor_sync(0xffffffffu, ps, o);
        pd += __shfl_xor_sync(0xffffffffu, pd, o);
    }
    if ((lane & 7) == 0) {
        d_as[warp * 4 + head] = ps;
        d_ad[warp * 4 + head] = pd;
    }
}

// ---------------- fused ONLINE softmax + aggregation + elu + residual ----------------
// (R4 version — best known; do not fatten this loop.)
__global__ void agg_k(int sel) {
    const float* __restrict__ hin = sel ? d_hB : d_hA;
    float* __restrict__ hout = sel ? d_hA : d_hB;
    int n = (blockIdx.x * blockDim.x + threadIdx.x) >> 5;
    if (n >= N_NODES) return;
    int lane = threadIdx.x & 31;
    int head = lane >> 3;

    float ad = d_ad[n * 4 + head];
    float amax = lrelu(d_as[n * 4 + head] + ad);   // self logit
    int beg = d_rowptr[n], end = d_rowptr[n + 1];

    float den = 1.f;                               // exp(self - self)
    float4 zv = ((const float4*)d_z)[n * 32 + lane];
    float4 S0 = zv;
    float4 S1 = zv;

#pragma unroll 2
    for (int e = beg; e < end; e++) {
        int s = __ldg(&d_col[e]);
        float l = lrelu(__ldg(&d_as[s * 4 + head]) + ad);
        float nm = fmaxf(amax, l);
        float c = __expf(amax - nm);
        float w = __expf(l - nm);
        amax = nm;
        float4 z2 = ((const float4*)d_z)[s * 32 + lane];
        den = fmaf(den, c, w);
        S0.x += z2.x; S0.y += z2.y; S0.z += z2.z; S0.w += z2.w;
        S1.x = fmaf(S1.x, c, w * z2.x);
        S1.y = fmaf(S1.y, c, w * z2.y);
        S1.z = fmaf(S1.z, c, w * z2.z);
        S1.w = fmaf(S1.w, c, w * z2.w);
    }
    float inv = 1.f / den;
    float4 r = ((const float4*)hin)[n * 32 + lane];
    float4 o;
    o.x = eluf(fmaf(S1.x, inv, S0.x)) + r.x;
    o.y = eluf(fmaf(S1.y, inv, S0.y)) + r.y;
    o.z = eluf(fmaf(S1.z, inv, S0.z)) + r.z;
    o.w = eluf(fmaf(S1.w, inv, S0.w)) + r.w;
    ((float4*)hout)[n * 32 + lane] = o;
}

// ---------------- graph readout ----------------
__global__ void readout_k() {
    int warp = (blockIdx.x * blockDim.x + threadIdx.x) >> 5;
    int lane = threadIdx.x & 31;
    int n0 = warp * 64;
    if (n0 >= N_NODES) return;
    int n1 = min(n0 + 64, N_NODES);
    int gcur = d_gid[n0];
    float4 acc = make_float4(0.f, 0.f, 0.f, 0.f);
    int run = 0;
    for (int n = n0; n < n1; n++) {
        int g = d_gid[n];
        if (g != gcur) {
            atomicAdd(&d_gsum[gcur * D + lane * 4 + 0], acc.x);
            atomicAdd(&d_gsum[gcur * D + lane * 4 + 1], acc.y);
            atomicAdd(&d_gsum[gcur * D + lane * 4 + 2], acc.z);
            atomicAdd(&d_gsum[gcur * D + lane * 4 + 3], acc.w);
            if (lane == 0) atomicAdd(&d_gcnt[gcur], run);
            acc = make_float4(0.f, 0.f, 0.f, 0.f);
            run = 0; gcur = g;
        }
        float4 v = ((const float4*)d_hA)[n * 32 + lane];
        acc.x += v.x; acc.y += v.y; acc.z += v.z; acc.w += v.w;
        run++;
    }
    atomicAdd(&d_gsum[gcur * D + lane * 4 + 0], acc.x);
    atomicAdd(&d_gsum[gcur * D + lane * 4 + 1], acc.y);
    atomicAdd(&d_gsum[gcur * D + lane * 4 + 2], acc.z);
    atomicAdd(&d_gsum[gcur * D + lane * 4 + 3], acc.w);
    if (lane == 0) atomicAdd(&d_gcnt[gcur], run);
}

// ---------------- MLP readout ----------------
__global__ void mlp_k(const float* __restrict__ w0, const float* __restrict__ b0,
                      const float* __restrict__ w1, const float* __restrict__ b1,
                      float* __restrict__ y) {
    int b = blockIdx.x;
    int j = threadIdx.x;            // 64 hidden units
    float inv = 1.f / fmaxf((float)d_gcnt[b], 1.f);
    float acc = b0[j];
    for (int k = 0; k < D; k++) {
        float g = fmaxf(d_gsum[b * D + k] * inv, 0.f);
        acc = fmaf(g, w0[k * 64 + j], acc);
    }
    float t = fmaxf(acc, 0.f) * w1[j];
    __shared__ float sh[64];
    sh[j] = t;
    __syncthreads();
    for (int off = 32; off > 0; off >>= 1) {
        if (j < off) sh[j] += sh[j + off];
        __syncthreads();
    }
    if (j == 0) y[b] = sh[0] + b1[0];
}

// ---------------- launcher ----------------
extern "C" void kernel_launch(void* const* d_in, const int* in_sizes, int n_in,
                              void* d_out, int out_size) {
    const void*  edge  = d_in[1];
    const void*  ptr   = d_in[2];
    const float* emb   = (const float*)d_in[3];
    const float* lin_w = (const float*)d_in[4];
    const float* att_s = (const float*)d_in[5];
    const float* att_d = (const float*)d_in[6];
    const float* w0    = (const float*)d_in[7];
    const float* b0    = (const float*)d_in[8];
    const float* w1    = (const float*)d_in[9];
    const float* b1    = (const float*)d_in[10];
    float* y = (float*)d_out;

    decode_k<<<EB + SCAN_NBLK + 65, 256>>>(edge, ptr, emb, lin_w);
    scan_k<<<SCAN_NBLK, 256>>>();
    fill_h1_k<<<EB + WB, 256>>>(emb);

    for (int l = 1; l < 3; l++) {
        int sel = l - 1;   // 0: hA->hB, 1: hB->hA
        gemm_k<<<(N_NODES + 127) / 128, 512>>>(lin_w + l * D * D, sel);
        att_k<<<WB, 256>>>(att_s + l * NHEAD * DH, att_d + l * NHEAD * DH);
        agg_k<<<WB, 256>>>(sel);
    }

    readout_k<<<((N_NODES + 63) / 64 * 32 + 255) / 256, 256>>>();
    mlp_k<<<B_GR, 64>>>(w0, b0, w1, b1, y);
}